// round 2
// baseline (speedup 1.0000x reference)
#include <cuda_runtime.h>
#include <cuda_fp16.h>
#include <cstdint>

// GPTQ int4 dequant GEMM: out[M,N] = x[M,K] @ W[K,N].
// Harness dtype contract: fp16 arrays are delivered as float32.
//   x: float32 [M,K], qweight: int32 [K/8,N], scales: float32 [G,N],
//   qzeros: int32 [G,N/8], g_idx: int32 [K] (== k/128, folded into indexing),
//   out: float32 [M,N] (values rounded through fp16 to match reference).
//
// W[k,n] = scales[k/128, n] * (((qweight[k/8,n] >> ((k%8)*4)) & 15)
//                              - (((qzeros[k/128, n/8] >> ((n%8)*4)) & 15) + 1))
//
// 128x128x32 CTA tile, 256 threads (8 warps = 4m x 2n), warp tile 32x64 via
// mma.sync.m16n8k16. Double-buffered smem (half); A register-staged
// (LDG fp32 -> cvt -> STS half), B dequantized in registers -> smem.

#define Mdim 4096
#define Kdim 4096
#define Ndim 11008
#define BM 128
#define BN 128
#define BK 32
#define ALD 40    // A smem row stride in halves
#define BLD 136   // B smem row stride in halves
#define KTILES (Kdim / BK)   // 128

__device__ __forceinline__ unsigned sptr(const void* p) {
    return (unsigned)__cvta_generic_to_shared(p);
}
__device__ __forceinline__ void ldmA(uint32_t r[4], unsigned a) {
    asm volatile("ldmatrix.sync.aligned.m8n8.x4.shared.b16 {%0,%1,%2,%3}, [%4];\n"
        : "=r"(r[0]), "=r"(r[1]), "=r"(r[2]), "=r"(r[3]) : "r"(a));
}
__device__ __forceinline__ void ldmBt(uint32_t r[4], unsigned a) {
    asm volatile("ldmatrix.sync.aligned.m8n8.x4.trans.shared.b16 {%0,%1,%2,%3}, [%4];\n"
        : "=r"(r[0]), "=r"(r[1]), "=r"(r[2]), "=r"(r[3]) : "r"(a));
}
__device__ __forceinline__ void mma16816(float c[4], const uint32_t a[4], const uint32_t b[2]) {
    asm volatile(
        "mma.sync.aligned.m16n8k16.row.col.f32.f16.f16.f32 "
        "{%0,%1,%2,%3}, {%4,%5,%6,%7}, {%8,%9}, {%0,%1,%2,%3};\n"
        : "+f"(c[0]), "+f"(c[1]), "+f"(c[2]), "+f"(c[3])
        : "r"(a[0]), "r"(a[1]), "r"(a[2]), "r"(a[3]), "r"(b[0]), "r"(b[1]));
}
__device__ __forceinline__ float r16(float v) {
    return __half2float(__float2half_rn(v));
}

__global__ __launch_bounds__(256)
void gptq_gemm_kernel(const float* __restrict__ x,
                      const int*   __restrict__ qw,
                      const float* __restrict__ sc,
                      const int*   __restrict__ qz,
                      float*       __restrict__ out)
{
    __shared__ __half As[2][BM * ALD];
    __shared__ __half Bs[2][BK * BLD];

    const int tid  = threadIdx.x;
    const int wid  = tid >> 5;
    const int lane = tid & 31;
    const int n0 = blockIdx.x * BN;
    const int m0 = blockIdx.y * BM;

    // ---- A staging mapping: one row, 16 fp32 per thread ----
    const int arow  = tid >> 1;                // 0..127
    const int acolf = (tid & 1) << 4;          // 0 or 16 (floats)
    const float4* gA4 = (const float4*)(x + (size_t)(m0 + arow) * Kdim) + (acolf >> 2);
    __half* sArow[2] = { &As[0][arow * ALD + acolf], &As[1][arow * ALD + acolf] };

    // ---- B dequant mapping: 2 packed int32s (cols nl, nl+1) per thread ----
    const int kk8 = tid >> 6;                  // 0..3 (k-local / 8)
    const int nl  = (tid << 1) & 127;          // even local col
    const int gcol = n0 + nl;
    const int2* gQbase = (const int2*)(qw + (size_t)kk8 * Ndim + gcol);
    const int zsh0 = (nl & 7) * 4;

    // ---- warp tiling ----
    const int wm = wid >> 1;                   // 0..3
    const int wn = wid & 1;                    // 0..1

    unsigned aAddr[2][2];
    unsigned bAddr[2][4];
    {
        const int l15 = lane & 15;
        const int hi8 = (lane >> 4) << 3;
        #pragma unroll
        for (int bu = 0; bu < 2; bu++) {
            #pragma unroll
            for (int mt = 0; mt < 2; mt++)
                aAddr[bu][mt] = sptr(&As[bu][(wm * 32 + mt * 16 + l15) * ALD + hi8]);
            #pragma unroll
            for (int p = 0; p < 4; p++)
                bAddr[bu][p] = sptr(&Bs[bu][l15 * BLD + wn * 64 + p * 16 + hi8]);
        }
    }

    float acc[2][8][4];
    #pragma unroll
    for (int mt = 0; mt < 2; mt++)
        #pragma unroll
        for (int nt = 0; nt < 8; nt++)
            #pragma unroll
            for (int i = 0; i < 4; i++) acc[mt][nt][i] = 0.f;

    // staging registers
    float4 av[4];
    int q0s, q1s, z0s, z1s;
    float s0s, s1s;

    // ---- tile loaders ----
    auto ldg_tile = [&](int it) {
        #pragma unroll
        for (int u = 0; u < 4; u++)
            av[u] = gA4[it * 8 + u];            // 32 floats/row per tile -> 8 float4
        int2 q = gQbase[(size_t)(it * 2) * Ndim / 2 ? 0 : 0]; // placeholder (not used)
        (void)q;
        const int2* gQ = (const int2*)((const int*)gQbase + (size_t)(it * 4) * Ndim);
        int2 qq = *gQ;
        q0s = qq.x; q1s = qq.y;
        const int g = it >> 2;
        float2 s2 = *(const float2*)(sc + (size_t)g * Ndim + gcol);
        s0s = s2.x; s1s = s2.y;
        int qzw = qz[(size_t)g * (Ndim / 8) + (gcol >> 3)];
        z0s = ((qzw >> zsh0) & 15) + 1;
        z1s = ((qzw >> (zsh0 + 4)) & 15) + 1;
    };
    auto sts_tile = [&](int bu) {
        // A: convert 16 fp32 -> 16 half, 2 x 16B stores
        __half2 hh[8];
        #pragma unroll
        for (int u = 0; u < 4; u++) {
            hh[2 * u]     = __floats2half2_rn(av[u].x, av[u].y);
            hh[2 * u + 1] = __floats2half2_rn(av[u].z, av[u].w);
        }
        *(uint4*)(sArow[bu])     = *(uint4*)&hh[0];
        *(uint4*)(sArow[bu] + 8) = *(uint4*)&hh[4];
        // B: dequant 2 columns x 8 k-rows
        #pragma unroll
        for (int j = 0; j < 8; j++) {
            int w0 = (q0s >> (4 * j)) & 15;
            int w1 = (q1s >> (4 * j)) & 15;
            *(__half2*)&Bs[bu][(kk8 * 8 + j) * BLD + nl] =
                __floats2half2_rn((float)(w0 - z0s) * s0s, (float)(w1 - z1s) * s1s);
        }
    };

    // ---------------- prologue ----------------
    ldg_tile(0);
    sts_tile(0);
    __syncthreads();

    // ---------------- mainloop ----------------
    for (int it = 0; it < KTILES; ++it) {
        const int cur = it & 1;
        const int nx  = cur ^ 1;
        const bool has_next = (it + 1 < KTILES);

        if (has_next) ldg_tile(it + 1);        // LDGs overlap with MMAs below

        #pragma unroll
        for (int ks = 0; ks < 2; ks++) {
            const int k16 = ks * 16;
            uint32_t a[2][4];
            #pragma unroll
            for (int mt = 0; mt < 2; mt++)
                ldmA(a[mt], aAddr[cur][mt] + k16 * 2);

            uint32_t b[8][2];
            #pragma unroll
            for (int p = 0; p < 4; p++) {
                uint32_t r[4];
                ldmBt(r, bAddr[cur][p] + k16 * BLD * 2);
                b[2 * p][0] = r[0]; b[2 * p][1] = r[1];
                b[2 * p + 1][0] = r[2]; b[2 * p + 1][1] = r[3];
            }

            #pragma unroll
            for (int mt = 0; mt < 2; mt++)
                #pragma unroll
                for (int nt = 0; nt < 8; nt++)
                    mma16816(acc[mt][nt], a[mt], b[nt]);
        }

        if (has_next) sts_tile(nx);
        __syncthreads();
    }

    // ---------------- epilogue (fp32 out, rounded through fp16) ----------------
    const int r = lane >> 2;
    const int c = (lane & 3) << 1;
    #pragma unroll
    for (int mt = 0; mt < 2; mt++) {
        #pragma unroll
        for (int nt = 0; nt < 8; nt++) {
            const size_t row = (size_t)(m0 + wm * 32 + mt * 16 + r);
            const size_t col = (size_t)(n0 + wn * 64 + nt * 8 + c);
            float* p0 = out + row * Ndim + col;
            *(float2*)p0 = make_float2(r16(acc[mt][nt][0]), r16(acc[mt][nt][1]));
            *(float2*)(p0 + 8 * (size_t)Ndim) =
                make_float2(r16(acc[mt][nt][2]), r16(acc[mt][nt][3]));
        }
    }
}

extern "C" void kernel_launch(void* const* d_in, const int* in_sizes, int n_in,
                              void* d_out, int out_size)
{
    const float* x  = (const float*)d_in[0];
    const int*   qw = (const int*)d_in[1];
    const float* sc = (const float*)d_in[2];
    const int*   qz = (const int*)d_in[3];
    // d_in[4] = g_idx: always k/128 here; folded into indexing.
    float* out = (float*)d_out;

    dim3 grid(Ndim / BN, Mdim / BM);   // (86, 32)
    gptq_gemm_kernel<<<grid, 256>>>(x, qw, sc, qz, out);
}

// round 3
// speedup vs baseline: 1.6859x; 1.6859x over previous
#include <cuda_runtime.h>
#include <cuda_fp16.h>
#include <cstdint>

// GPTQ int4 dequant GEMM: out[M,N] = x[M,K] @ W[K,N].
// Inputs (harness upcasts fp16 arrays to fp32):
//   x: f32 [M,K], qweight: i32 [K/8,N], scales: f32 [G,N], qzeros: i32 [G,N/8],
//   g_idx: i32 [K] (== k/128, folded), out: f32 [M,N] (rounded through fp16).
//
// Stage 1: cvt_x_kernel converts x -> fp16 into __device__ g_xh (one-time per launch).
// Stage 2: 128x128x32 CTA tile, 256 thr (8 warps = 4m x 2n), warp tile 32x64,
//          mma.sync.m16n8k16. A via cp.async (fp16), B dequantized
//          (magic-number int4->fp16) into smem. Double buffered. 2 CTAs/SM.

#define Mdim 4096
#define Kdim 4096
#define Ndim 11008
#define BM 128
#define BN 128
#define BK 32
#define ALD 40
#define BLD 136
#define KTILES (Kdim / BK)

__device__ __half g_xh[(size_t)Mdim * Kdim];   // 32 MB fp16 copy of x

__global__ __launch_bounds__(256)
void cvt_x_kernel(const float* __restrict__ x)
{
    size_t i = ((size_t)blockIdx.x * blockDim.x + threadIdx.x) * 8;
    float4 a = *(const float4*)(x + i);
    float4 b = *(const float4*)(x + i + 4);
    __half2 h[4];
    h[0] = __floats2half2_rn(a.x, a.y);
    h[1] = __floats2half2_rn(a.z, a.w);
    h[2] = __floats2half2_rn(b.x, b.y);
    h[3] = __floats2half2_rn(b.z, b.w);
    *(uint4*)(g_xh + i) = *(uint4*)h;
}

__device__ __forceinline__ unsigned sptr(const void* p) {
    return (unsigned)__cvta_generic_to_shared(p);
}
__device__ __forceinline__ void cpa16(unsigned d, const void* s) {
    asm volatile("cp.async.cg.shared.global [%0], [%1], 16;\n" :: "r"(d), "l"(s));
}
__device__ __forceinline__ void cp_commit() { asm volatile("cp.async.commit_group;\n"); }
__device__ __forceinline__ void cp_wait0()  { asm volatile("cp.async.wait_group 0;\n"); }

__device__ __forceinline__ void ldmA(uint32_t r[4], unsigned a) {
    asm volatile("ldmatrix.sync.aligned.m8n8.x4.shared.b16 {%0,%1,%2,%3}, [%4];\n"
        : "=r"(r[0]), "=r"(r[1]), "=r"(r[2]), "=r"(r[3]) : "r"(a));
}
__device__ __forceinline__ void ldmBt(uint32_t r[4], unsigned a) {
    asm volatile("ldmatrix.sync.aligned.m8n8.x4.trans.shared.b16 {%0,%1,%2,%3}, [%4];\n"
        : "=r"(r[0]), "=r"(r[1]), "=r"(r[2]), "=r"(r[3]) : "r"(a));
}
__device__ __forceinline__ void mma16816(float c[4], const uint32_t a[4], const uint32_t b[2]) {
    asm volatile(
        "mma.sync.aligned.m16n8k16.row.col.f32.f16.f16.f32 "
        "{%0,%1,%2,%3}, {%4,%5,%6,%7}, {%8,%9}, {%0,%1,%2,%3};\n"
        : "+f"(c[0]), "+f"(c[1]), "+f"(c[2]), "+f"(c[3])
        : "r"(a[0]), "r"(a[1]), "r"(a[2]), "r"(a[3]), "r"(b[0]), "r"(b[1]));
}
__device__ __forceinline__ float r16(float v) {
    return __half2float(__float2half_rn(v));
}

__global__ __launch_bounds__(256, 2)
void gptq_gemm_kernel(const int*   __restrict__ qw,
                      const float* __restrict__ sc,
                      const int*   __restrict__ qz,
                      float*       __restrict__ out)
{
    __shared__ __half As[2][BM * ALD];
    __shared__ __half Bs[2][BK * BLD];

    const int tid  = threadIdx.x;
    const int wid  = tid >> 5;
    const int lane = tid & 31;
    const int n0 = blockIdx.x * BN;
    const int m0 = blockIdx.y * BM;

    // ---- A cp.async mapping: one row, 16 halfs (2x16B) per thread ----
    const int arow  = tid >> 1;
    const int acolh = (tid & 1) << 4;          // 0 or 16 halfs
    const __half* gAh = g_xh + (size_t)(m0 + arow) * Kdim + acolh;
    const unsigned sA[2] = {
        sptr(&As[0][arow * ALD + acolh]),
        sptr(&As[1][arow * ALD + acolh])
    };

    // ---- B dequant mapping: 2 packed int32s (cols nl, nl+1) per thread ----
    const int kk8 = tid >> 6;                  // 0..3
    const int nl  = (tid << 1) & 127;          // even local col
    const int gcol = n0 + nl;
    const int* gQbase = qw + (size_t)kk8 * Ndim + gcol;
    const int zsh0 = (nl & 7) * 4;

    // ---- warp tiling: 4m x 2n, warp tile 32x64 ----
    const int wm = wid >> 1;
    const int wn = wid & 1;

    unsigned aAddr[2][2];
    unsigned bAddr[2][4];
    {
        const int l15 = lane & 15;
        const int hi8 = (lane >> 4) << 3;
        #pragma unroll
        for (int bu = 0; bu < 2; bu++) {
            #pragma unroll
            for (int mt = 0; mt < 2; mt++)
                aAddr[bu][mt] = sptr(&As[bu][(wm * 32 + mt * 16 + l15) * ALD + hi8]);
            #pragma unroll
            for (int p = 0; p < 4; p++)
                bAddr[bu][p] = sptr(&Bs[bu][l15 * BLD + wn * 64 + p * 16 + hi8]);
        }
    }

    float acc[2][8][4];
    #pragma unroll
    for (int mt = 0; mt < 2; mt++)
        #pragma unroll
        for (int nt = 0; nt < 8; nt++)
            #pragma unroll
            for (int i = 0; i < 4; i++) acc[mt][nt][i] = 0.f;

    // staging for next B tile
    uint32_t q0s, q1s;
    __half2 s2h, bias2;

    auto ldgB = [&](int it) {
        const int2 qq = *(const int2*)(gQbase + (size_t)(it * 4) * Ndim);
        q0s = (uint32_t)qq.x; q1s = (uint32_t)qq.y;
        const int g = it >> 2;
        float2 sf = *(const float2*)(sc + (size_t)g * Ndim + gcol);
        int qzw = qz[(size_t)g * (Ndim / 8) + (gcol >> 3)];
        int z0 = ((qzw >> zsh0) & 15) + 1;
        int z1 = ((qzw >> (zsh0 + 4)) & 15) + 1;
        s2h   = __floats2half2_rn(sf.x, sf.y);
        bias2 = __floats2half2_rn(1024.f + (float)z0, 1024.f + (float)z1);
    };
    auto stsB = [&](int bu) {
        #pragma unroll
        for (int j = 0; j < 8; j++) {
            uint32_t nib = ((q0s >> (4 * j)) & 15u)
                         | (((q1s >> (4 * j)) & 15u) << 16)
                         | 0x64006400u;                     // half2(1024+w0, 1024+w1)
            __half2 hv = *(__half2*)&nib;
            *(__half2*)&Bs[bu][(kk8 * 8 + j) * BLD + nl] =
                __hmul2(__hsub2(hv, bias2), s2h);           // s*(w-z) in fp16
        }
    };
    auto cpaA = [&](int it, int bu) {
        cpa16(sA[bu],      gAh + it * BK);
        cpa16(sA[bu] + 16, gAh + it * BK + 8);
        cp_commit();
    };

    // ---------------- prologue ----------------
    cpaA(0, 0);
    ldgB(0);
    stsB(0);
    cp_wait0();
    __syncthreads();

    // ---------------- mainloop ----------------
    for (int it = 0; it < KTILES; ++it) {
        const int cur = it & 1;
        const int nx  = cur ^ 1;
        const bool has_next = (it + 1 < KTILES);

        if (has_next) {
            cpaA(it + 1, nx);
            ldgB(it + 1);          // LDGs overlap with MMAs below
        }

        #pragma unroll
        for (int ks = 0; ks < 2; ks++) {
            const int k16 = ks * 16;
            uint32_t a[2][4];
            #pragma unroll
            for (int mt = 0; mt < 2; mt++)
                ldmA(a[mt], aAddr[cur][mt] + k16 * 2);

            uint32_t b[8][2];
            #pragma unroll
            for (int p = 0; p < 4; p++) {
                uint32_t r[4];
                ldmBt(r, bAddr[cur][p] + k16 * BLD * 2);
                b[2 * p][0] = r[0]; b[2 * p][1] = r[1];
                b[2 * p + 1][0] = r[2]; b[2 * p + 1][1] = r[3];
            }

            #pragma unroll
            for (int mt = 0; mt < 2; mt++)
                #pragma unroll
                for (int nt = 0; nt < 8; nt++)
                    mma16816(acc[mt][nt], a[mt], b[nt]);
        }

        if (has_next) stsB(nx);
        cp_wait0();
        __syncthreads();
    }

    // ---------------- epilogue ----------------
    const int r = lane >> 2;
    const int c = (lane & 3) << 1;
    #pragma unroll
    for (int mt = 0; mt < 2; mt++) {
        #pragma unroll
        for (int nt = 0; nt < 8; nt++) {
            const size_t row = (size_t)(m0 + wm * 32 + mt * 16 + r);
            const size_t col = (size_t)(n0 + wn * 64 + nt * 8 + c);
            float* p0 = out + row * Ndim + col;
            *(float2*)p0 = make_float2(r16(acc[mt][nt][0]), r16(acc[mt][nt][1]));
            *(float2*)(p0 + 8 * (size_t)Ndim) =
                make_float2(r16(acc[mt][nt][2]), r16(acc[mt][nt][3]));
        }
    }
}

extern "C" void kernel_launch(void* const* d_in, const int* in_sizes, int n_in,
                              void* d_out, int out_size)
{
    const float* x  = (const float*)d_in[0];
    const int*   qw = (const int*)d_in[1];
    const float* sc = (const float*)d_in[2];
    const int*   qz = (const int*)d_in[3];
    float* out = (float*)d_out;

    cvt_x_kernel<<<(Mdim * (size_t)Kdim) / (256 * 8), 256>>>(x);

    dim3 grid(Ndim / BN, Mdim / BM);   // (86, 32)
    gptq_gemm_kernel<<<grid, 256>>>(qw, sc, qz, out);
}